// round 15
// baseline (speedup 1.0000x reference)
#include <cuda_runtime.h>
#include <cuda_fp16.h>
#include <math.h>
#include <stdint.h>

// Problem constants
#define Bq   8
#define Nq   8192
#define Cq   256
#define Hq   8
#define Dq   32
#define Sq   32
#define HIDq 1024
#define Mq   (Bq * Nq)        // 65536 rows
#define BHq  (Bq * Hq)        // 64
#define KV_CHUNKS 64
#define QKVW 768

// GEMM tiling (fp16 mma m16n8k16), BM=128 x BN=64, 3 CTAs/SM target
#define BM 128
#define BN 64
#define BKH 64                              // K-halves per tile (128 B/row)
#define STAGE_BYTES ((BM + BN) * BKH * 2)   // 24 KB
#define GEMM_SMEM (2 * STAGE_BYTES)         // 48 KB
#define PADK 136                            // kv-epilogue smem row pitch (halfs)

// ---------------- scratch (static device arrays; no allocation) -------------
__device__ __half g_xln_h[Mq * Cq];
__device__ __half g_fx_h [Mq * Cq];
__device__ __half g_q_h  [(size_t)Mq * Cq];
__device__ float  g_ekvp [KV_CHUNKS * BHq * Sq * Dq];
__device__ float  g_csp  [KV_CHUNKS * BHq * Sq];
__device__ __half g_KW   [Bq * Cq * Cq];
__device__ __half g_h_h  [Mq * Cq];
__device__ __half g_y_h  [Mq * Cq];
__device__ __half g_hid_h[Mq * HIDq];
__device__ __half g_WQKV [QKVW * Cq];   // q rows 0-255 | head h: k at 256+h*64, v at +32
__device__ float  g_bqkv [QKVW];
__device__ __half g_W1_h [HIDq * Cq];
__device__ __half g_W2_h [Cq * HIDq];

// ------------------------------ PTX helpers ---------------------------------
__device__ __forceinline__ uint32_t smem_u32(const void* p) {
    uint32_t a;
    asm("{ .reg .u64 t; cvta.to.shared.u64 t, %1; cvt.u32.u64 %0, t; }"
        : "=r"(a) : "l"(p));
    return a;
}
__device__ __forceinline__ void cp_async16(uint32_t dst, const void* src) {
    asm volatile("cp.async.cg.shared.global [%0], [%1], 16;"
                 :: "r"(dst), "l"(src));
}
__device__ __forceinline__ void cp_commit() {
    asm volatile("cp.async.commit_group;");
}
template <int N>
__device__ __forceinline__ void cp_wait() {
    asm volatile("cp.async.wait_group %0;" :: "n"(N));
}
__device__ __forceinline__ void ldsm4(uint32_t* r, uint32_t addr) {
    asm volatile("ldmatrix.sync.aligned.m8n8.x4.shared.b16 {%0,%1,%2,%3}, [%4];"
                 : "=r"(r[0]), "=r"(r[1]), "=r"(r[2]), "=r"(r[3]) : "r"(addr));
}
__device__ __forceinline__ void mma_f16(float* c, const uint32_t* a, const uint32_t* b) {
    asm volatile(
        "mma.sync.aligned.m16n8k16.row.col.f32.f16.f16.f32 "
        "{%0,%1,%2,%3}, {%4,%5,%6,%7}, {%8,%9}, {%0,%1,%2,%3};"
        : "+f"(c[0]), "+f"(c[1]), "+f"(c[2]), "+f"(c[3])
        : "r"(a[0]), "r"(a[1]), "r"(a[2]), "r"(a[3]), "r"(b[0]), "r"(b[1]));
}

// ---------------- fp32 -> fp16 weight conversion (one launch) ----------------
#define F4_W1 (HIDq * Cq / 4)
#define F4_W2 (Cq * HIDq / 4)
#define F4_TOTAL (F4_W1 + F4_W2)

__global__ void f2h_all_kernel(const float* __restrict__ W1,
                               const float* __restrict__ W2,
                               __half* oW1, __half* oW2) {
    int i = blockIdx.x * 256 + threadIdx.x;
    if (i >= F4_TOTAL) return;
    const float* src; __half* dst; int j;
    if (i < F4_W1) { src = W1; dst = oW1; j = i; }
    else           { src = W2; dst = oW2; j = i - F4_W1; }
    float4 v = ((const float4*)src)[j];
    ((__half2*)dst)[j * 2]     = __floats2half2_rn(v.x, v.y);
    ((__half2*)dst)[j * 2 + 1] = __floats2half2_rn(v.z, v.w);
}

// ------- composite weights: q rows h*32+s; k_h rows 256+h*64+s; v_h +32 ----
__global__ __launch_bounds__(256) void compose_kernel(
    const float* __restrict__ Wq, const float* __restrict__ Wk,
    const float* __restrict__ Wv, const float* __restrict__ Wx,
    const float* __restrict__ bx,
    __half* __restrict__ WQKV, float* __restrict__ bqkv) {
    int type = blockIdx.x >> 3;    // 0=q,1=k,2=v
    int h    = blockIdx.x & 7;
    const float* Wsm_g = (type == 0) ? Wq : (type == 1) ? Wk : Wv;
    int rowbase = (type == 0) ? h * 32
                : 256 + h * 64 + (type == 2 ? 32 : 0);
    __shared__ float Wsm[32][32];
    __shared__ float bxs[32];
    int tid = threadIdx.x;
    for (int i = tid; i < 1024; i += 256) Wsm[i >> 5][i & 31] = Wsm_g[i];
    if (tid < 32) bxs[tid] = bx[h * 32 + tid];
    __syncthreads();

    int j = tid;
    float xc[32];
#pragma unroll
    for (int d = 0; d < 32; d++) xc[d] = Wx[(size_t)(h * 32 + d) * Cq + j];
#pragma unroll
    for (int s = 0; s < 32; s++) {
        float a = 0.f;
#pragma unroll
        for (int d = 0; d < 32; d++) a += Wsm[s][d] * xc[d];
        WQKV[(size_t)(rowbase + s) * Cq + j] = __float2half_rn(a);
    }
    if (tid < 32) {
        float a = 0.f;
#pragma unroll
        for (int d = 0; d < 32; d++) a += Wsm[tid][d] * bxs[d];
        bqkv[rowbase + tid] = a;
    }
}

// -------- LayerNorm: warp per row, vectorized 16B I/O; optional fx16 --------
template <typename Tin, int WFX>
__global__ __launch_bounds__(256) void ln_kernel(
    const Tin* __restrict__ x,
    const float* __restrict__ w, const float* __restrict__ bb,
    __half* __restrict__ out, __half* __restrict__ fxo) {
    int row  = blockIdx.x * 8 + (threadIdx.x >> 5);
    int lane = threadIdx.x & 31;
    float v[8];
    if (sizeof(Tin) == 4) {
        const float4* p = (const float4*)((const float*)x + (size_t)row * Cq) + lane * 2;
        float4 a = p[0], c = p[1];
        v[0]=a.x; v[1]=a.y; v[2]=a.z; v[3]=a.w;
        v[4]=c.x; v[5]=c.y; v[6]=c.z; v[7]=c.w;
    } else {
        uint4 u = *(const uint4*)((const __half*)x + (size_t)row * Cq + lane * 8);
        const __half2* hh = (const __half2*)&u;
#pragma unroll
        for (int i = 0; i < 4; i++) {
            float2 f = __half22float2(hh[i]);
            v[2 * i] = f.x; v[2 * i + 1] = f.y;
        }
    }
    float s = 0.f, s2 = 0.f;
#pragma unroll
    for (int i = 0; i < 8; i++) { s += v[i]; s2 += v[i] * v[i]; }
#pragma unroll
    for (int o = 16; o > 0; o >>= 1) {
        s  += __shfl_xor_sync(0xffffffffu, s,  o);
        s2 += __shfl_xor_sync(0xffffffffu, s2, o);
    }
    float mu  = s * (1.f / Cq);
    float var = s2 * (1.f / Cq) - mu * mu;
    float rs  = rsqrtf(var + 1e-5f);

    const float4* wp = (const float4*)w + lane * 2;
    const float4* bp = (const float4*)bb + lane * 2;
    float4 w0 = wp[0], w1 = wp[1], b0 = bp[0], b1 = bp[1];
    float wr[8] = {w0.x, w0.y, w0.z, w0.w, w1.x, w1.y, w1.z, w1.w};
    float br[8] = {b0.x, b0.y, b0.z, b0.w, b1.x, b1.y, b1.z, b1.w};

    __half2 oh[4];
#pragma unroll
    for (int i = 0; i < 4; i++)
        oh[i] = __floats2half2_rn((v[2*i]   - mu) * rs * wr[2*i]   + br[2*i],
                                  (v[2*i+1] - mu) * rs * wr[2*i+1] + br[2*i+1]);
    *(uint4*)(out + (size_t)row * Cq + lane * 8) = *(uint4*)oh;

    if (WFX) {
        __half2 fh[4];
#pragma unroll
        for (int i = 0; i < 4; i++)
            fh[i] = __floats2half2_rn(v[2*i], v[2*i+1]);
        *(uint4*)(fxo + (size_t)row * Cq + lane * 8) = *(uint4*)fh;
    }
}

// ---------- shared mainloop: BM=128 x BN=64, 8 warps (4m x 2n), 32x32 -------
// acc[2][4][4] per warp. Returns with accumulators filled.
#define GEMM_MAINLOOP(Ab, Wb, K, LDA)                                          \
    auto load_tile = [&](int stage, int kt) {                                  \
        uint32_t aoff = sbase + stage * STAGE_BYTES;                           \
        uint32_t boff = aoff + BM * BKH * 2;                                   \
        int k0 = kt * BKH;                                                     \
        _Pragma("unroll")                                                      \
        for (int i = 0; i < 4; i++) {                                          \
            int idx  = i * 256 + tid;                                          \
            int row  = idx >> 3;                                               \
            int grp  = idx & 7;                                                \
            int phys = grp ^ (row & 7);                                        \
            cp_async16(aoff + (row * 8 + phys) * 16,                           \
                       &Ab[(size_t)row * (LDA) + k0 + grp * 8]);               \
        }                                                                      \
        _Pragma("unroll")                                                      \
        for (int i = 0; i < 2; i++) {                                          \
            int idx  = i * 256 + tid;                                          \
            int row  = idx >> 3;                                               \
            int grp  = idx & 7;                                                \
            int phys = grp ^ (row & 7);                                        \
            cp_async16(boff + (row * 8 + phys) * 16,                           \
                       &Wb[(size_t)row * (K) + k0 + grp * 8]);                 \
        }                                                                      \
    };                                                                         \
    load_tile(0, 0);                                                           \
    cp_commit();                                                               \
    int ntiles = (K) / BKH;                                                    \
    for (int kt = 0; kt < ntiles; kt++) {                                      \
        int cur = kt & 1;                                                      \
        if (kt + 1 < ntiles) {                                                 \
            load_tile(cur ^ 1, kt + 1);                                        \
            cp_commit();                                                       \
            cp_wait<1>();                                                      \
        } else {                                                               \
            cp_wait<0>();                                                      \
        }                                                                      \
        __syncthreads();                                                       \
        uint32_t sAb = sbase + cur * STAGE_BYTES;                              \
        uint32_t sBb = sAb + BM * BKH * 2;                                     \
        _Pragma("unroll")                                                      \
        for (int ks = 0; ks < 4; ks++) {                                       \
            uint32_t af[2][4];                                                 \
            _Pragma("unroll")                                                  \
            for (int mt = 0; mt < 2; mt++) {                                   \
                int row = warp_m * 32 + mt * 16 + (lane & 15);                 \
                int kg  = 2 * ks + (lane >> 4);                                \
                ldsm4(af[mt], sAb + (row * 8 + (kg ^ (row & 7))) * 16);        \
            }                                                                  \
            uint32_t bf[2][4];                                                 \
            _Pragma("unroll")                                                  \
            for (int p = 0; p < 2; p++) {                                      \
                int n  = warp_n * 32 + p * 16 + (lane >> 4) * 8 + (lane & 7);  \
                int kg = 2 * ks + ((lane >> 3) & 1);                           \
                ldsm4(bf[p], sBb + (n * 8 + (kg ^ (n & 7))) * 16);             \
            }                                                                  \
            _Pragma("unroll")                                                  \
            for (int mt = 0; mt < 2; mt++)                                     \
                _Pragma("unroll")                                              \
                for (int nt = 0; nt < 4; nt++)                                 \
                    mma_f16(acc[mt][nt], af[mt], &bf[nt >> 1][(nt & 1) * 2]);  \
        }                                                                      \
        __syncthreads();                                                       \
    }

// ================= qkv GEMM: q-softmax + in-CTA kv partials =================
// grid (12, 512). x<4: q tiles -> softmax -> g_q_h.  x>=4: head x-4 kv block.
__global__ __launch_bounds__(256, 3) void qkv_gemm_kernel(
    const __half* __restrict__ A, const __half* __restrict__ W,
    const float* __restrict__ bias, __half* __restrict__ qo) {
    extern __shared__ char smem[];
    const int K = Cq;
    int tid  = threadIdx.x;
    int wid  = tid >> 5, lane = tid & 31;
    int g = lane >> 2, q = lane & 3;
    int warp_m = wid >> 1;     // 0..3 -> 32 rows
    int warp_n = wid & 1;      // 0..1 -> 32 cols

    uint32_t sbase = smem_u32(smem);
    const __half* Ab = A + (size_t)blockIdx.y * BM * K;
    const __half* Wb = W + (size_t)blockIdx.x * BN * K;

    float acc[2][4][4];
#pragma unroll
    for (int mt = 0; mt < 2; mt++)
#pragma unroll
        for (int nt = 0; nt < 4; nt++)
#pragma unroll
            for (int i = 0; i < 4; i++) acc[mt][nt][i] = 0.f;

    GEMM_MAINLOOP(Ab, Wb, K, K)

    int nBase = blockIdx.x * BN + warp_n * 32;
    float bvs[4][2];
#pragma unroll
    for (int nt = 0; nt < 4; nt++) {
        int c0 = nBase + nt * 8 + q * 2;
        bvs[nt][0] = bias[c0];
        bvs[nt][1] = bias[c0 + 1];
    }

    if (blockIdx.x < 4) {
        // ---- q branch: warp owns one head's 32 slices; fused softmax ----
        int mBase = blockIdx.y * BM + warp_m * 32;
#pragma unroll
        for (int mt = 0; mt < 2; mt++) {
#pragma unroll
            for (int half = 0; half < 2; half++) {
                float ex[4][2];
                float rs = 0.f;
#pragma unroll
                for (int nt = 0; nt < 4; nt++) {
                    ex[nt][0] = __expf(acc[mt][nt][half * 2 + 0] + bvs[nt][0]);
                    ex[nt][1] = __expf(acc[mt][nt][half * 2 + 1] + bvs[nt][1]);
                    rs += ex[nt][0] + ex[nt][1];
                }
                rs += __shfl_xor_sync(0xffffffffu, rs, 1);
                rs += __shfl_xor_sync(0xffffffffu, rs, 2);
                float inv = 1.f / rs;
                int r = mBase + mt * 16 + half * 8 + g;
#pragma unroll
                for (int nt = 0; nt < 4; nt++) {
                    size_t off = (size_t)r * Cq + nBase + nt * 8 + q * 2;
                    *(__half2*)&qo[off] =
                        __floats2half2_rn(ex[nt][0] * inv, ex[nt][1] * inv);
                }
            }
        }
        return;
    }

    // ---- kv branch: one head per CTA; cols 0..31 = k, 32..63 = v ----
    __half* smh = (__half*)smem;
    int is_v = warp_n;

    for (int i = tid; i < 16 * PADK; i += 256) {
        int rr = i / PADK, cc = i % PADK;
        smh[(64 + rr) * PADK + cc] =
            (rr == 0 && cc < 128) ? __float2half(1.f) : __half(0);
    }

    __half* hb = smh + (is_v ? 32 : 0) * PADK;
#pragma unroll
    for (int nt = 0; nt < 4; nt++) {
        int c = nt * 8 + q * 2;
#pragma unroll
        for (int mt = 0; mt < 2; mt++) {
#pragma unroll
            for (int half = 0; half < 2; half++) {
                int t = warp_m * 32 + mt * 16 + half * 8 + g;
                float v0 = acc[mt][nt][half * 2 + 0] + bvs[nt][0];
                float v1 = acc[mt][nt][half * 2 + 1] + bvs[nt][1];
                if (!is_v) { v0 = __expf(v0); v1 = __expf(v1); }
                hb[c * PADK + t]       = __float2half_rn(v0);
                hb[(c + 1) * PADK + t] = __float2half_rn(v1);
            }
        }
    }
    __syncthreads();

    if (wid == 0) {
        uint32_t ek_base = smem_u32(smh);
        uint32_t v_base  = ek_base + 32 * PADK * 2;
        float a2[2][5][4];
#pragma unroll
        for (int mt = 0; mt < 2; mt++)
#pragma unroll
            for (int nt = 0; nt < 5; nt++)
#pragma unroll
                for (int i = 0; i < 4; i++) a2[mt][nt][i] = 0.f;

#pragma unroll
        for (int ks = 0; ks < 8; ks++) {
            uint32_t af[2][4];
#pragma unroll
            for (int mt = 0; mt < 2; mt++) {
                int r_ = mt * 16 + (lane & 15);
                int kg = 2 * ks + (lane >> 4);
                ldsm4(af[mt], ek_base + (r_ * PADK + kg * 8) * 2);
            }
            uint32_t bf[3][4];
#pragma unroll
            for (int p = 0; p < 3; p++) {
                int n_ = p * 16 + (lane >> 4) * 8 + (lane & 7);
                int kg = 2 * ks + ((lane >> 3) & 1);
                ldsm4(bf[p], v_base + (n_ * PADK + kg * 8) * 2);
            }
#pragma unroll
            for (int mt = 0; mt < 2; mt++)
#pragma unroll
                for (int nt = 0; nt < 5; nt++)
                    mma_f16(a2[mt][nt], af[mt], &bf[nt >> 1][(nt & 1) * 2]);
        }

        int b  = blockIdx.y >> 6;
        int ch = blockIdx.y & 63;
        int bh = b * Hq + (blockIdx.x - 4);
        size_t pbase = ((size_t)ch * BHq + bh) * (Sq * Dq);
#pragma unroll
        for (int mt = 0; mt < 2; mt++) {
#pragma unroll
            for (int half = 0; half < 2; half++) {
                int s = mt * 16 + g + half * 8;
#pragma unroll
                for (int nt = 0; nt < 4; nt++) {
                    int d = nt * 8 + q * 2;
                    *(float2*)&g_ekvp[pbase + s * 32 + d] =
                        make_float2(a2[mt][nt][half * 2], a2[mt][nt][half * 2 + 1]);
                }
                if (q == 0)
                    g_csp[((size_t)ch * BHq + bh) * Sq + s] = a2[mt][4][half * 2];
            }
        }
    }
}

// ------------- generic fp16 mma GEMM (steps 4,6,7) --------------------------
__device__ __forceinline__ float gelu_exact(float v) {
    return 0.5f * v * (1.f + erff(v * 0.70710678118654752f));
}

template <int EPI, int OUT16, int RES16>
__global__ __launch_bounds__(256, 3) void hgemm_kernel(
    const __half* __restrict__ A, const __half* __restrict__ W,
    const float* __restrict__ bias, const void* __restrict__ res,
    float* __restrict__ Cout, __half* __restrict__ Cout16,
    int Ncols, int K, int lda, size_t sA, size_t sW, size_t sC) {
    extern __shared__ char smem[];
    int tid  = threadIdx.x;
    int wid  = tid >> 5, lane = tid & 31;
    int g = lane >> 2, q = lane & 3;
    int warp_m = wid >> 1;
    int warp_n = wid & 1;
    size_t zoffC = sC * blockIdx.z;

    uint32_t sbase = smem_u32(smem);
    const __half* Ab = A + sA * blockIdx.z + (size_t)blockIdx.y * BM * lda;
    const __half* Wb = W + sW * blockIdx.z + (size_t)blockIdx.x * BN * K;

    float acc[2][4][4];
#pragma unroll
    for (int mt = 0; mt < 2; mt++)
#pragma unroll
        for (int nt = 0; nt < 4; nt++)
#pragma unroll
            for (int i = 0; i < 4; i++) acc[mt][nt][i] = 0.f;

    GEMM_MAINLOOP(Ab, Wb, K, lda)

    int mBase = blockIdx.y * BM + warp_m * 32;
    int nBase = blockIdx.x * BN + warp_n * 32;
    float bvs[4][2];
#pragma unroll
    for (int nt = 0; nt < 4; nt++) {
        int c0 = nBase + nt * 8 + q * 2;
        bvs[nt][0] = bias[c0];
        bvs[nt][1] = bias[c0 + 1];
    }

#pragma unroll
    for (int nt = 0; nt < 4; nt++) {
        int c0 = nBase + nt * 8 + q * 2;
#pragma unroll
        for (int mt = 0; mt < 2; mt++) {
            int r0 = mBase + mt * 16 + g;
#pragma unroll
            for (int half = 0; half < 2; half++) {
                int r = r0 + half * 8;
                size_t off = (size_t)r * Ncols + c0 + zoffC;
                float v0 = acc[mt][nt][half * 2 + 0] + bvs[nt][0];
                float v1 = acc[mt][nt][half * 2 + 1] + bvs[nt][1];
                if (EPI == 1) {
                    if (RES16) {
                        __half2 rr = *(const __half2*)((const __half*)res + off);
                        v0 += __low2float(rr); v1 += __high2float(rr);
                    } else {
                        float2 rr = *(const float2*)((const float*)res + off);
                        v0 += rr.x; v1 += rr.y;
                    }
                }
                if (EPI == 2) { v0 = gelu_exact(v0); v1 = gelu_exact(v1); }
                if (OUT16) {
                    *(__half2*)&Cout16[off] = __floats2half2_rn(v0, v1);
                } else {
                    *(float2*)&Cout[off] = make_float2(v0, v1);
                }
            }
        }
    }
}

// ---- kv finalize + KW = kv @ Wo_h^T  (fp16 [b][c][h*32+s]) ------------------
__global__ __launch_bounds__(256) void kvw_kernel(const float* __restrict__ Wo,
                                                  __half* __restrict__ KW) {
    int bh = blockIdx.x;
    int b = bh >> 3, h = bh & 7;
    int tid = threadIdx.x;
    __shared__ float kvs[32][33];
    __shared__ float rcs[32];

    if (tid < 32) {
        float c = 0.f;
#pragma unroll
        for (int ch = 0; ch < KV_CHUNKS; ch++)
            c += g_csp[((size_t)ch * BHq + bh) * Sq + tid];
        rcs[tid] = 1.f / c;
    }
    __syncthreads();
#pragma unroll
    for (int rep = 0; rep < 4; rep++) {
        int idx = tid + rep * 256;
        int s = idx >> 5, d = idx & 31;
        float vsum = 0.f;
#pragma unroll
        for (int ch = 0; ch < KV_CHUNKS; ch++)
            vsum += g_ekvp[((size_t)ch * BHq + bh) * (Sq * Dq) + idx];
        kvs[s][d] = vsum * rcs[s];
    }
    __syncthreads();

    int c = tid;
    float wo[32];
#pragma unroll
    for (int d = 0; d < 32; d++) wo[d] = Wo[(size_t)c * Cq + h * 32 + d];
    __half2 outv[16];
#pragma unroll
    for (int sp = 0; sp < 16; sp++) {
        float a0 = 0.f, a1 = 0.f;
#pragma unroll
        for (int d = 0; d < 32; d++) {
            a0 += kvs[2 * sp][d] * wo[d];
            a1 += kvs[2 * sp + 1][d] * wo[d];
        }
        outv[sp] = __floats2half2_rn(a0, a1);
    }
    uint4* dst = (uint4*)&KW[((size_t)b * Cq + c) * Cq + h * 32];
#pragma unroll
    for (int i = 0; i < 4; i++) dst[i] = ((uint4*)outv)[i];
}

// ---------------------------- launcher ---------------------------------------
extern "C" void kernel_launch(void* const* d_in, const int* in_sizes, int n_in,
                              void* d_out, int out_size) {
    const float* fx   = (const float*)d_in[0];
    const float* ln1w = (const float*)d_in[1];
    const float* ln1b = (const float*)d_in[2];
    const float* Wx   = (const float*)d_in[3];
    const float* bx   = (const float*)d_in[4];
    const float* Wqp  = (const float*)d_in[5];
    const float* Wkp  = (const float*)d_in[6];
    const float* Wvp  = (const float*)d_in[7];
    const float* Wo   = (const float*)d_in[8];
    const float* bo   = (const float*)d_in[9];
    const float* ln2w = (const float*)d_in[10];
    const float* ln2b = (const float*)d_in[11];
    const float* W1   = (const float*)d_in[12];
    const float* b1   = (const float*)d_in[13];
    const float* W2   = (const float*)d_in[14];
    const float* b2   = (const float*)d_in[15];
    float* out = (float*)d_out;

    __half *p_xln, *p_fx16, *p_q, *p_KW, *p_h, *p_y, *p_hid, *p_WQKV, *p_W1, *p_W2;
    float  *p_bqkv;
    cudaGetSymbolAddress((void**)&p_xln,  g_xln_h);
    cudaGetSymbolAddress((void**)&p_fx16, g_fx_h);
    cudaGetSymbolAddress((void**)&p_q,    g_q_h);
    cudaGetSymbolAddress((void**)&p_KW,   g_KW);
    cudaGetSymbolAddress((void**)&p_h,    g_h_h);
    cudaGetSymbolAddress((void**)&p_y,    g_y_h);
    cudaGetSymbolAddress((void**)&p_hid,  g_hid_h);
    cudaGetSymbolAddress((void**)&p_WQKV, g_WQKV);
    cudaGetSymbolAddress((void**)&p_bqkv, g_bqkv);
    cudaGetSymbolAddress((void**)&p_W1,   g_W1_h);
    cudaGetSymbolAddress((void**)&p_W2,   g_W2_h);

    cudaFuncSetAttribute(qkv_gemm_kernel,     cudaFuncAttributeMaxDynamicSharedMemorySize, GEMM_SMEM);
    cudaFuncSetAttribute(hgemm_kernel<1,1,1>, cudaFuncAttributeMaxDynamicSharedMemorySize, GEMM_SMEM);
    cudaFuncSetAttribute(hgemm_kernel<2,1,0>, cudaFuncAttributeMaxDynamicSharedMemorySize, GEMM_SMEM);
    cudaFuncSetAttribute(hgemm_kernel<1,0,1>, cudaFuncAttributeMaxDynamicSharedMemorySize, GEMM_SMEM);

    // 0) weight conversion + composite q/k/v weights (per-head k/v layout)
    f2h_all_kernel<<<(F4_TOTAL + 255) / 256, 256>>>(W1, W2, p_W1, p_W2);
    compose_kernel<<<24, 256>>>(Wqp, Wkp, Wvp, Wx, bx, p_WQKV, p_bqkv);

    // 1) LN1 -> fp16 (also emits fx as fp16 for residual)
    ln_kernel<float, 1><<<Mq / 8, 256>>>(fx, ln1w, ln1b, p_xln, p_fx16);
    // 2) qkv GEMM: q softmax -> g_q_h; k/v -> in-CTA kv partials
    qkv_gemm_kernel<<<dim3(QKVW / BN, Mq / BM), 256, GEMM_SMEM>>>(
        p_xln, p_WQKV, p_bqkv, p_q);
    // 3) finalize kv + KW = kv @ Wo^T
    kvw_kernel<<<BHq, 256>>>(Wo, p_KW);
    // 4) h = q @ KW^T + bo + fx  (batched over b; h fp16, fp16 residual)
    hgemm_kernel<1,1,1><<<dim3(Cq / BN, Nq / BM, Bq), 256, GEMM_SMEM>>>(
        p_q, p_KW, bo, p_fx16, nullptr, p_h, Cq, Cq, Cq,
        (size_t)Nq * Cq, (size_t)Cq * Cq, (size_t)Nq * Cq);
    // 5) LN2 (fp16 in) -> fp16
    ln_kernel<__half, 0><<<Mq / 8, 256>>>(p_h, ln2w, ln2b, p_y, nullptr);
    // 6) hid = gelu(y @ W1^T + b1)
    hgemm_kernel<2,1,0><<<dim3(HIDq / BN, Mq / BM, 1), 256, GEMM_SMEM>>>(
        p_y, p_W1, b1, nullptr, nullptr, p_hid, HIDq, Cq, Cq, 0, 0, 0);
    // 7) out = hid @ W2^T + b2 + h  (h fp16 residual, fp32 out)
    hgemm_kernel<1,0,1><<<dim3(Cq / BN, Mq / BM, 1), 256, GEMM_SMEM>>>(
        p_hid, p_W2, b2, p_h, out, nullptr, Cq, HIDq, HIDq, 0, 0, 0);
}

// round 16
// speedup vs baseline: 1.0773x; 1.0773x over previous
#include <cuda_runtime.h>
#include <cuda_fp16.h>
#include <math.h>
#include <stdint.h>

// Problem constants
#define Bq   8
#define Nq   8192
#define Cq   256
#define Hq   8
#define Dq   32
#define Sq   32
#define HIDq 1024
#define Mq   (Bq * Nq)        // 65536 rows
#define BHq  (Bq * Hq)        // 64
#define KV_CHUNKS 64
#define QKVW 768

// GEMM tiling (fp16 mma m16n8k16), 2-stage pipeline  (R13 geometry)
#define BM 128
#define BN 128
#define BKH 64                          // K-halves per tile (128 bytes/row)
#define STAGE_BYTES (2 * BM * BKH * 2)  // A tile + B tile = 32KB
#define GEMM_SMEM (2 * STAGE_BYTES)     // 2 stages = 64KB
#define PADK 136                        // kv-epilogue smem row pitch (halfs)

// ---------------- scratch (static device arrays; no allocation) -------------
__device__ __half g_xln_h[Mq * Cq];
__device__ __half g_fx_h [Mq * Cq];             // fp16 copy of fx (residual)
__device__ __half g_q_h  [(size_t)Mq * Cq];     // normalized q only
__device__ float  g_ekvp [KV_CHUNKS * BHq * Sq * Dq];
__device__ float  g_csp  [KV_CHUNKS * BHq * Sq];
__device__ __half g_KW   [Bq * Cq * Cq];
__device__ __half g_h_h  [Mq * Cq];             // residual spine, fp16
__device__ __half g_y_h  [Mq * Cq];
__device__ __half g_hid_h[Mq * HIDq];
__device__ __half g_WQKV [QKVW * Cq];           // q | per-head-pair [k0 v0 k1 v1]
__device__ float  g_bqkv [QKVW];
__device__ __half g_W1_h [HIDq * Cq];
__device__ __half g_W2_h [Cq * HIDq];

// ------------------------------ PTX helpers ---------------------------------
__device__ __forceinline__ uint32_t smem_u32(const void* p) {
    uint32_t a;
    asm("{ .reg .u64 t; cvta.to.shared.u64 t, %1; cvt.u32.u64 %0, t; }"
        : "=r"(a) : "l"(p));
    return a;
}
__device__ __forceinline__ void cp_async16(uint32_t dst, const void* src) {
    asm volatile("cp.async.cg.shared.global [%0], [%1], 16;"
                 :: "r"(dst), "l"(src));
}
__device__ __forceinline__ void cp_commit() {
    asm volatile("cp.async.commit_group;");
}
template <int N>
__device__ __forceinline__ void cp_wait() {
    asm volatile("cp.async.wait_group %0;" :: "n"(N));
}
__device__ __forceinline__ void ldsm4(uint32_t* r, uint32_t addr) {
    asm volatile("ldmatrix.sync.aligned.m8n8.x4.shared.b16 {%0,%1,%2,%3}, [%4];"
                 : "=r"(r[0]), "=r"(r[1]), "=r"(r[2]), "=r"(r[3]) : "r"(addr));
}
__device__ __forceinline__ void mma_f16(float* c, const uint32_t* a, const uint32_t* b) {
    asm volatile(
        "mma.sync.aligned.m16n8k16.row.col.f32.f16.f16.f32 "
        "{%0,%1,%2,%3}, {%4,%5,%6,%7}, {%8,%9}, {%0,%1,%2,%3};"
        : "+f"(c[0]), "+f"(c[1]), "+f"(c[2]), "+f"(c[3])
        : "r"(a[0]), "r"(a[1]), "r"(a[2]), "r"(a[3]), "r"(b[0]), "r"(b[1]));
}

// -------- merged prep: compose (blocks 0..23) + W1/W2 f2h (blocks 24+) ------
#define F4_W1 (HIDq * Cq / 4)
#define F4_W2 (Cq * HIDq / 4)
#define F4_TOTAL (F4_W1 + F4_W2)
#define PREP_BLOCKS (24 + (F4_TOTAL + 255) / 256)

__global__ __launch_bounds__(256) void prep_kernel(
    const float* __restrict__ Wq, const float* __restrict__ Wk,
    const float* __restrict__ Wv, const float* __restrict__ Wx,
    const float* __restrict__ bx,
    const float* __restrict__ W1, const float* __restrict__ W2,
    __half* __restrict__ WQKV, float* __restrict__ bqkv,
    __half* oW1, __half* oW2) {
    int tid = threadIdx.x;
    if (blockIdx.x >= 24) {
        int i = (blockIdx.x - 24) * 256 + tid;
        if (i >= F4_TOTAL) return;
        const float* src; __half* dst; int j;
        if (i < F4_W1) { src = W1; dst = oW1; j = i; }
        else           { src = W2; dst = oW2; j = i - F4_W1; }
        float4 v = ((const float4*)src)[j];
        ((__half2*)dst)[j * 2]     = __floats2half2_rn(v.x, v.y);
        ((__half2*)dst)[j * 2 + 1] = __floats2half2_rn(v.z, v.w);
        return;
    }
    // compose: q rows h*32+s ; k_h rows 256+(h>>1)*128+(h&1)*64+s ; v_h +32
    int type = blockIdx.x >> 3;    // 0=q,1=k,2=v
    int h    = blockIdx.x & 7;
    const float* Wsm_g = (type == 0) ? Wq : (type == 1) ? Wk : Wv;
    int rowbase = (type == 0) ? h * 32
                : 256 + (h >> 1) * 128 + (h & 1) * 64 + (type == 2 ? 32 : 0);
    __shared__ float Wsm[32][32];
    __shared__ float bxs[32];
    for (int i = tid; i < 1024; i += 256) Wsm[i >> 5][i & 31] = Wsm_g[i];
    if (tid < 32) bxs[tid] = bx[h * 32 + tid];
    __syncthreads();

    int j = tid;
    float xc[32];
#pragma unroll
    for (int d = 0; d < 32; d++) xc[d] = Wx[(size_t)(h * 32 + d) * Cq + j];
#pragma unroll
    for (int s = 0; s < 32; s++) {
        float a = 0.f;
#pragma unroll
        for (int d = 0; d < 32; d++) a += Wsm[s][d] * xc[d];
        WQKV[(size_t)(rowbase + s) * Cq + j] = __float2half_rn(a);
    }
    if (tid < 32) {
        float a = 0.f;
#pragma unroll
        for (int d = 0; d < 32; d++) a += Wsm[tid][d] * bxs[d];
        bqkv[rowbase + tid] = a;
    }
}

// -------- LayerNorm: warp per row, vectorized 16B I/O; optional fx16 --------
template <typename Tin, int WFX>
__global__ __launch_bounds__(256) void ln_kernel(
    const Tin* __restrict__ x,
    const float* __restrict__ w, const float* __restrict__ bb,
    __half* __restrict__ out, __half* __restrict__ fxo) {
    int row  = blockIdx.x * 8 + (threadIdx.x >> 5);
    int lane = threadIdx.x & 31;
    float v[8];
    if (sizeof(Tin) == 4) {
        const float4* p = (const float4*)((const float*)x + (size_t)row * Cq) + lane * 2;
        float4 a = p[0], c = p[1];
        v[0]=a.x; v[1]=a.y; v[2]=a.z; v[3]=a.w;
        v[4]=c.x; v[5]=c.y; v[6]=c.z; v[7]=c.w;
    } else {
        uint4 u = *(const uint4*)((const __half*)x + (size_t)row * Cq + lane * 8);
        const __half2* hh = (const __half2*)&u;
#pragma unroll
        for (int i = 0; i < 4; i++) {
            float2 f = __half22float2(hh[i]);
            v[2 * i] = f.x; v[2 * i + 1] = f.y;
        }
    }
    float s = 0.f, s2 = 0.f;
#pragma unroll
    for (int i = 0; i < 8; i++) { s += v[i]; s2 += v[i] * v[i]; }
#pragma unroll
    for (int o = 16; o > 0; o >>= 1) {
        s  += __shfl_xor_sync(0xffffffffu, s,  o);
        s2 += __shfl_xor_sync(0xffffffffu, s2, o);
    }
    float mu  = s * (1.f / Cq);
    float var = s2 * (1.f / Cq) - mu * mu;
    float rs  = rsqrtf(var + 1e-5f);

    const float4* wp = (const float4*)w + lane * 2;
    const float4* bp = (const float4*)bb + lane * 2;
    float4 w0 = wp[0], w1 = wp[1], b0 = bp[0], b1 = bp[1];
    float wr[8] = {w0.x, w0.y, w0.z, w0.w, w1.x, w1.y, w1.z, w1.w};
    float br[8] = {b0.x, b0.y, b0.z, b0.w, b1.x, b1.y, b1.z, b1.w};

    __half2 oh[4];
#pragma unroll
    for (int i = 0; i < 4; i++)
        oh[i] = __floats2half2_rn((v[2*i]   - mu) * rs * wr[2*i]   + br[2*i],
                                  (v[2*i+1] - mu) * rs * wr[2*i+1] + br[2*i+1]);
    *(uint4*)(out + (size_t)row * Cq + lane * 8) = *(uint4*)oh;

    if (WFX) {
        __half2 fh[4];
#pragma unroll
        for (int i = 0; i < 4; i++)
            fh[i] = __floats2half2_rn(v[2*i], v[2*i+1]);
        *(uint4*)(fxo + (size_t)row * Cq + lane * 8) = *(uint4*)fh;
    }
}

// ================= qkv GEMM: q-softmax + in-CTA kv partials =================
// grid (6, 512). x<2: q tiles -> softmax -> g_q_h.  x>=2: head-pair kv blocks.
__global__ __launch_bounds__(256, 2) void qkv_gemm_kernel(
    const __half* __restrict__ A, const __half* __restrict__ W,
    const float* __restrict__ bias, __half* __restrict__ qo) {
    extern __shared__ char smem[];
    const int K = Cq;
    int tid  = threadIdx.x;
    int wid  = tid >> 5, lane = tid & 31;
    int g = lane >> 2, q = lane & 3;
    int warp_m = wid >> 2;
    int warp_n = wid & 3;

    uint32_t sbase = smem_u32(smem);
    const __half* Ab = A + (size_t)blockIdx.y * BM * K;
    const __half* Wb = W + (size_t)blockIdx.x * BN * K;

    float acc[4][4][4];
#pragma unroll
    for (int mt = 0; mt < 4; mt++)
#pragma unroll
        for (int nt = 0; nt < 4; nt++)
#pragma unroll
            for (int i = 0; i < 4; i++) acc[mt][nt][i] = 0.f;

    auto load_tile = [&](int stage, int kt) {
        uint32_t aoff = sbase + stage * STAGE_BYTES;
        uint32_t boff = aoff + BM * BKH * 2;
        int k0 = kt * BKH;
#pragma unroll
        for (int i = 0; i < 4; i++) {
            int idx  = i * 256 + tid;
            int row  = idx >> 3;
            int grp  = idx & 7;
            int phys = grp ^ (row & 7);
            cp_async16(aoff + (row * 8 + phys) * 16, &Ab[(size_t)row * K + k0 + grp * 8]);
            cp_async16(boff + (row * 8 + phys) * 16, &Wb[(size_t)row * K + k0 + grp * 8]);
        }
    };

    load_tile(0, 0);
    cp_commit();

    const int ntiles = K / BKH;   // 4
    for (int kt = 0; kt < ntiles; kt++) {
        int cur = kt & 1;
        if (kt + 1 < ntiles) {
            load_tile(cur ^ 1, kt + 1);
            cp_commit();
            cp_wait<1>();
        } else {
            cp_wait<0>();
        }
        __syncthreads();

        uint32_t sAb = sbase + cur * STAGE_BYTES;
        uint32_t sBb = sAb + BM * BKH * 2;

#pragma unroll
        for (int ks = 0; ks < 4; ks++) {
            uint32_t af[4][4];
#pragma unroll
            for (int mt = 0; mt < 4; mt++) {
                int row = warp_m * 64 + mt * 16 + (lane & 15);
                int kg  = 2 * ks + (lane >> 4);
                ldsm4(af[mt], sAb + (row * 8 + (kg ^ (row & 7))) * 16);
            }
            uint32_t bf[2][4];
#pragma unroll
            for (int p = 0; p < 2; p++) {
                int n  = warp_n * 32 + p * 16 + (lane >> 4) * 8 + (lane & 7);
                int kg = 2 * ks + ((lane >> 3) & 1);
                ldsm4(bf[p], sBb + (n * 8 + (kg ^ (n & 7))) * 16);
            }
#pragma unroll
            for (int mt = 0; mt < 4; mt++)
#pragma unroll
                for (int nt = 0; nt < 4; nt++)
                    mma_f16(acc[mt][nt], af[mt], &bf[nt >> 1][(nt & 1) * 2]);
        }
        __syncthreads();
    }

    int nBase = blockIdx.x * BN + warp_n * 32;
    float bvs[4][2];
#pragma unroll
    for (int nt = 0; nt < 4; nt++) {
        int c0 = nBase + nt * 8 + q * 2;
        bvs[nt][0] = bias[c0];
        bvs[nt][1] = bias[c0 + 1];
    }

    if (blockIdx.x < 2) {
        // ---- q branch: fused softmax, write fp16 into g_q_h [token][256] ----
        int mBase = blockIdx.y * BM + warp_m * 64;
#pragma unroll
        for (int mt = 0; mt < 4; mt++) {
#pragma unroll
            for (int half = 0; half < 2; half++) {
                float ex[4][2];
                float rs = 0.f;
#pragma unroll
                for (int nt = 0; nt < 4; nt++) {
                    ex[nt][0] = __expf(acc[mt][nt][half * 2 + 0] + bvs[nt][0]);
                    ex[nt][1] = __expf(acc[mt][nt][half * 2 + 1] + bvs[nt][1]);
                    rs += ex[nt][0] + ex[nt][1];
                }
                rs += __shfl_xor_sync(0xffffffffu, rs, 1);
                rs += __shfl_xor_sync(0xffffffffu, rs, 2);
                float inv = 1.f / rs;
                int r = mBase + mt * 16 + half * 8 + g;
#pragma unroll
                for (int nt = 0; nt < 4; nt++) {
                    size_t off = (size_t)r * Cq + nBase + nt * 8 + q * 2;
                    *(__half2*)&qo[off] =
                        __floats2half2_rn(ex[nt][0] * inv, ex[nt][1] * inv);
                }
            }
        }
        return;
    }

    // ---- kv branch: build ekT/vT in smem, 2 warps do kv-partial MMA ----
    __half* smh = (__half*)smem;
    int h_local = warp_n >> 1;
    int is_v    = warp_n & 1;

    for (int i = tid; i < 2 * 16 * PADK; i += 256) {
        int hl = i / (16 * PADK);
        int rr = (i / PADK) % 16;
        int cc = i % PADK;
        smh[hl * 80 * PADK + (64 + rr) * PADK + cc] =
            (rr == 0 && cc < 128) ? __float2half(1.f) : __half(0);
    }

    __half* hb = smh + h_local * 80 * PADK + (is_v ? 32 : 0) * PADK;
#pragma unroll
    for (int nt = 0; nt < 4; nt++) {
        int c = nt * 8 + q * 2;
#pragma unroll
        for (int mt = 0; mt < 4; mt++) {
#pragma unroll
            for (int half = 0; half < 2; half++) {
                int t = warp_m * 64 + mt * 16 + half * 8 + g;
                float v0 = acc[mt][nt][half * 2 + 0] + bvs[nt][0];
                float v1 = acc[mt][nt][half * 2 + 1] + bvs[nt][1];
                if (!is_v) { v0 = __expf(v0); v1 = __expf(v1); }
                hb[c * PADK + t]       = __float2half_rn(v0);
                hb[(c + 1) * PADK + t] = __float2half_rn(v1);
            }
        }
    }
    __syncthreads();

    if (wid < 2) {
        uint32_t ek_base = smem_u32(smh + wid * 80 * PADK);
        uint32_t v_base  = ek_base + 32 * PADK * 2;
        float a2[2][5][4];
#pragma unroll
        for (int mt = 0; mt < 2; mt++)
#pragma unroll
            for (int nt = 0; nt < 5; nt++)
#pragma unroll
                for (int i = 0; i < 4; i++) a2[mt][nt][i] = 0.f;

#pragma unroll
        for (int ks = 0; ks < 8; ks++) {
            uint32_t af[2][4];
#pragma unroll
            for (int mt = 0; mt < 2; mt++) {
                int r_ = mt * 16 + (lane & 15);
                int kg = 2 * ks + (lane >> 4);
                ldsm4(af[mt], ek_base + (r_ * PADK + kg * 8) * 2);
            }
            uint32_t bf[3][4];
#pragma unroll
            for (int p = 0; p < 3; p++) {
                int n_ = p * 16 + (lane >> 4) * 8 + (lane & 7);
                int kg = 2 * ks + ((lane >> 3) & 1);
                ldsm4(bf[p], v_base + (n_ * PADK + kg * 8) * 2);
            }
#pragma unroll
            for (int mt = 0; mt < 2; mt++)
#pragma unroll
                for (int nt = 0; nt < 5; nt++)
                    mma_f16(a2[mt][nt], af[mt], &bf[nt >> 1][(nt & 1) * 2]);
        }

        int b  = blockIdx.y >> 6;
        int ch = blockIdx.y & 63;
        int bh = b * Hq + (blockIdx.x - 2) * 2 + wid;
        size_t pbase = ((size_t)ch * BHq + bh) * (Sq * Dq);
#pragma unroll
        for (int mt = 0; mt < 2; mt++) {
#pragma unroll
            for (int half = 0; half < 2; half++) {
                int s = mt * 16 + g + half * 8;
#pragma unroll
                for (int nt = 0; nt < 4; nt++) {
                    int d = nt * 8 + q * 2;
                    *(float2*)&g_ekvp[pbase + s * 32 + d] =
                        make_float2(a2[mt][nt][half * 2], a2[mt][nt][half * 2 + 1]);
                }
                if (q == 0)
                    g_csp[((size_t)ch * BHq + bh) * Sq + s] = a2[mt][4][half * 2];
            }
        }
    }
}

// ------------- generic fp16 mma GEMM (steps 4,6,7) --------------------------
__device__ __forceinline__ float gelu_exact(float v) {
    return 0.5f * v * (1.f + erff(v * 0.70710678118654752f));
}

template <int EPI, int OUT16, int RES16>
__global__ __launch_bounds__(256) void hgemm_kernel(
    const __half* __restrict__ A, const __half* __restrict__ W,
    const float* __restrict__ bias, const void* __restrict__ res,
    float* __restrict__ Cout, __half* __restrict__ Cout16,
    int Ncols, int K, int lda, size_t sA, size_t sW, size_t sC) {
    extern __shared__ char smem[];
    int tid  = threadIdx.x;
    int wid  = tid >> 5, lane = tid & 31;
    int g = lane >> 2, q = lane & 3;
    int warp_m = wid >> 2;
    int warp_n = wid & 3;
    size_t zoffC = sC * blockIdx.z;

    uint32_t sbase = smem_u32(smem);
    const __half* Ab = A + sA * blockIdx.z + (size_t)blockIdx.y * BM * lda;
    const __half* Wb = W + sW * blockIdx.z + (size_t)blockIdx.x * BN * K;

    float acc[4][4][4];
#pragma unroll
    for (int mt = 0; mt < 4; mt++)
#pragma unroll
        for (int nt = 0; nt < 4; nt++)
#pragma unroll
            for (int i = 0; i < 4; i++) acc[mt][nt][i] = 0.f;

    int ntiles = K / BKH;

    auto load_tile = [&](int stage, int kt) {
        uint32_t aoff = sbase + stage * STAGE_BYTES;
        uint32_t boff = aoff + BM * BKH * 2;
        int k0 = kt * BKH;
#pragma unroll
        for (int i = 0; i < 4; i++) {
            int idx  = i * 256 + tid;
            int row  = idx >> 3;
            int grp  = idx & 7;
            int phys = grp ^ (row & 7);
            cp_async16(aoff + (row * 8 + phys) * 16, &Ab[(size_t)row * lda + k0 + grp * 8]);
            cp_async16(boff + (row * 8 + phys) * 16, &Wb[(size_t)row * K + k0 + grp * 8]);
        }
    };

    load_tile(0, 0);
    cp_commit();

    for (int kt = 0; kt < ntiles; kt++) {
        int cur = kt & 1;
        if (kt + 1 < ntiles) {
            load_tile(cur ^ 1, kt + 1);
            cp_commit();
            cp_wait<1>();
        } else {
            cp_wait<0>();
        }
        __syncthreads();

        uint32_t sAb = sbase + cur * STAGE_BYTES;
        uint32_t sBb = sAb + BM * BKH * 2;

#pragma unroll
        for (int ks = 0; ks < 4; ks++) {
            uint32_t af[4][4];
#pragma unroll
            for (int mt = 0; mt < 4; mt++) {
                int row = warp_m * 64 + mt * 16 + (lane & 15);
                int kg  = 2 * ks + (lane >> 4);
                ldsm4(af[mt], sAb + (row * 8 + (kg ^ (row & 7))) * 16);
            }
            uint32_t bf[2][4];
#pragma unroll
            for (int p = 0; p < 2; p++) {
                int n  = warp_n * 32 + p * 16 + (lane >> 4) * 8 + (lane & 7);
                int kg = 2 * ks + ((lane >> 3) & 1);
                ldsm4(bf[p], sBb + (n * 8 + (kg ^ (n & 7))) * 16);
            }
#pragma unroll
            for (int mt = 0; mt < 4; mt++)
#pragma unroll
                for (int nt = 0; nt < 4; nt++)
                    mma_f16(acc[mt][nt], af[mt], &bf[nt >> 1][(nt & 1) * 2]);
        }
        __syncthreads();
    }

    int mBase = blockIdx.y * BM + warp_m * 64;
    int nBase = blockIdx.x * BN + warp_n * 32;
    float bvs[4][2];
#pragma unroll
    for (int nt = 0; nt < 4; nt++) {
        int c0 = nBase + nt * 8 + q * 2;
        bvs[nt][0] = bias[c0];
        bvs[nt][1] = bias[c0 + 1];
    }

#pragma unroll
    for (int nt = 0; nt < 4; nt++) {
        int c0 = nBase + nt * 8 + q * 2;
#pragma unroll
        for (int mt = 0; mt < 4; mt++) {
            int r0 = mBase + mt * 16 + g;
#pragma unroll
            for (int half = 0; half < 2; half++) {
                int r = r0 + half * 8;
                size_t off = (size_t)r * Ncols + c0 + zoffC;
                float v0 = acc[mt][nt][half * 2 + 0] + bvs[nt][0];
                float v1 = acc[mt][nt][half * 2 + 1] + bvs[nt][1];
                if (EPI == 1) {
                    if (RES16) {
                        __half2 rr = *(const __half2*)((const __half*)res + off);
                        v0 += __low2float(rr); v1 += __high2float(rr);
                    } else {
                        float2 rr = *(const float2*)((const float*)res + off);
                        v0 += rr.x; v1 += rr.y;
                    }
                }
                if (EPI == 2) { v0 = gelu_exact(v0); v1 = gelu_exact(v1); }
                if (OUT16) {
                    *(__half2*)&Cout16[off] = __floats2half2_rn(v0, v1);
                } else {
                    *(float2*)&Cout[off] = make_float2(v0, v1);
                }
            }
        }
    }
}

// ---- kv finalize + KW = kv @ Wo_h^T  (fp16 [b][c][h*32+s]) ------------------
__global__ __launch_bounds__(256) void kvw_kernel(const float* __restrict__ Wo,
                                                  __half* __restrict__ KW) {
    int bh = blockIdx.x;
    int b = bh >> 3, h = bh & 7;
    int tid = threadIdx.x;
    __shared__ float kvs[32][33];
    __shared__ float rcs[32];

    if (tid < 32) {
        float c = 0.f;
#pragma unroll
        for (int ch = 0; ch < KV_CHUNKS; ch++)
            c += g_csp[((size_t)ch * BHq + bh) * Sq + tid];
        rcs[tid] = 1.f / c;
    }
    __syncthreads();
#pragma unroll
    for (int rep = 0; rep < 4; rep++) {
        int idx = tid + rep * 256;
        int s = idx >> 5, d = idx & 31;
        float vsum = 0.f;
#pragma unroll
        for (int ch = 0; ch < KV_CHUNKS; ch++)
            vsum += g_ekvp[((size_t)ch * BHq + bh) * (Sq * Dq) + idx];
        kvs[s][d] = vsum * rcs[s];
    }
    __syncthreads();

    int c = tid;
    float wo[32];
#pragma unroll
    for (int d = 0; d < 32; d++) wo[d] = Wo[(size_t)c * Cq + h * 32 + d];
    __half2 outv[16];
#pragma unroll
    for (int sp = 0; sp < 16; sp++) {
        float a0 = 0.f, a1 = 0.f;
#pragma unroll
        for (int d = 0; d < 32; d++) {
            a0 += kvs[2 * sp][d] * wo[d];
            a1 += kvs[2 * sp + 1][d] * wo[d];
        }
        outv[sp] = __floats2half2_rn(a0, a1);
    }
    uint4* dst = (uint4*)&KW[((size_t)b * Cq + c) * Cq + h * 32];
#pragma unroll
    for (int i = 0; i < 4; i++) dst[i] = ((uint4*)outv)[i];
}

// ---------------------------- launcher ---------------------------------------
extern "C" void kernel_launch(void* const* d_in, const int* in_sizes, int n_in,
                              void* d_out, int out_size) {
    const float* fx   = (const float*)d_in[0];
    const float* ln1w = (const float*)d_in[1];
    const float* ln1b = (const float*)d_in[2];
    const float* Wx   = (const float*)d_in[3];
    const float* bx   = (const float*)d_in[4];
    const float* Wqp  = (const float*)d_in[5];
    const float* Wkp  = (const float*)d_in[6];
    const float* Wvp  = (const float*)d_in[7];
    const float* Wo   = (const float*)d_in[8];
    const float* bo   = (const float*)d_in[9];
    const float* ln2w = (const float*)d_in[10];
    const float* ln2b = (const float*)d_in[11];
    const float* W1   = (const float*)d_in[12];
    const float* b1   = (const float*)d_in[13];
    const float* W2   = (const float*)d_in[14];
    const float* b2   = (const float*)d_in[15];
    float* out = (float*)d_out;

    __half *p_xln, *p_fx16, *p_q, *p_KW, *p_h, *p_y, *p_hid, *p_WQKV, *p_W1, *p_W2;
    float  *p_bqkv;
    cudaGetSymbolAddress((void**)&p_xln,  g_xln_h);
    cudaGetSymbolAddress((void**)&p_fx16, g_fx_h);
    cudaGetSymbolAddress((void**)&p_q,    g_q_h);
    cudaGetSymbolAddress((void**)&p_KW,   g_KW);
    cudaGetSymbolAddress((void**)&p_h,    g_h_h);
    cudaGetSymbolAddress((void**)&p_y,    g_y_h);
    cudaGetSymbolAddress((void**)&p_hid,  g_hid_h);
    cudaGetSymbolAddress((void**)&p_WQKV, g_WQKV);
    cudaGetSymbolAddress((void**)&p_bqkv, g_bqkv);
    cudaGetSymbolAddress((void**)&p_W1,   g_W1_h);
    cudaGetSymbolAddress((void**)&p_W2,   g_W2_h);

    cudaFuncSetAttribute(qkv_gemm_kernel,     cudaFuncAttributeMaxDynamicSharedMemorySize, GEMM_SMEM);
    cudaFuncSetAttribute(hgemm_kernel<1,1,1>, cudaFuncAttributeMaxDynamicSharedMemorySize, GEMM_SMEM);
    cudaFuncSetAttribute(hgemm_kernel<2,1,0>, cudaFuncAttributeMaxDynamicSharedMemorySize, GEMM_SMEM);
    cudaFuncSetAttribute(hgemm_kernel<1,0,1>, cudaFuncAttributeMaxDynamicSharedMemorySize, GEMM_SMEM);

    // 0) merged prep: composite q/k/v weights + W1/W2 fp16 conversion
    prep_kernel<<<PREP_BLOCKS, 256>>>(Wqp, Wkp, Wvp, Wx, bx, W1, W2,
                                      p_WQKV, p_bqkv, p_W1, p_W2);

    // 1) LN1 -> fp16 (also emits fx as fp16 for residual)
    ln_kernel<float, 1><<<Mq / 8, 256>>>(fx, ln1w, ln1b, p_xln, p_fx16);
    // 2) qkv GEMM: q softmax -> g_q_h; k/v -> in-CTA kv partials (no HBM k/v)
    qkv_gemm_kernel<<<dim3(QKVW / BN, Mq / BM), 256, GEMM_SMEM>>>(
        p_xln, p_WQKV, p_bqkv, p_q);
    // 3) finalize kv + KW = kv @ Wo^T
    kvw_kernel<<<BHq, 256>>>(Wo, p_KW);
    // 4) h = q @ KW^T + bo + fx  (batched over b; h fp16, fp16 residual)
    hgemm_kernel<1,1,1><<<dim3(Cq / BN, Nq / BM, Bq), 256, GEMM_SMEM>>>(
        p_q, p_KW, bo, p_fx16, nullptr, p_h, Cq, Cq, Cq,
        (size_t)Nq * Cq, (size_t)Cq * Cq, (size_t)Nq * Cq);
    // 5) LN2 (fp16 in) -> fp16
    ln_kernel<__half, 0><<<Mq / 8, 256>>>(p_h, ln2w, ln2b, p_y, nullptr);
    // 6) hid = gelu(y @ W1^T + b1)
    hgemm_kernel<2,1,0><<<dim3(HIDq / BN, Mq / BM, 1), 256, GEMM_SMEM>>>(
        p_y, p_W1, b1, nullptr, nullptr, p_hid, HIDq, Cq, Cq, 0, 0, 0);
    // 7) out = hid @ W2^T + b2 + h  (h fp16 residual, fp32 out)
    hgemm_kernel<1,0,1><<<dim3(Cq / BN, Mq / BM, 1), 256, GEMM_SMEM>>>(
        p_hid, p_W2, b2, p_h, out, nullptr, Cq, HIDq, HIDq, 0, 0, 0);
}